// round 9
// baseline (speedup 1.0000x reference)
#include <cuda_runtime.h>
#include <cuda_bf16.h>

// One-hot: x [8,1024] int32 -> out [8,1024,32000] fp32 (1.048 GB of stores).
// Uniform-chunk fill: ignore row structure for the zero stream. 65,536,000
// float4 = 64,000 blocks x 256 threads x 4 unconditional STG.128 — no tail,
// no predicates, perfectly balanced blocks. A 1024-float4 chunk overlaps at
// most 2 rows; the block checks those rows' hot slots and the thread that
// zeroed the hot slot overwrites one lane with 1.0f (same-thread
// same-address => ordered, no fence). Every hot slot lies in exactly one
// chunk, so exactly one block writes each 1.
//
// Granularity curve (kernel us): row 141.1 -> 1/2 139.6 -> 1/4 137.0 ->
// 1/8 136.4 -> this removes the last tail waste.

static constexpr int NUM_CLASS = 32000;
static constexpr int NC4       = NUM_CLASS / 4;        // 8000 float4 per row
static constexpr int ROWS      = 8 * 1024;             // 8192
static constexpr int CHUNK     = 1024;                 // float4 per block
static constexpr int THREADS   = 256;
static constexpr int ITERS     = CHUNK / THREADS;      // 4, exact
static constexpr int BLOCKS    = ROWS * NC4 / CHUNK;   // 64,000, exact

__global__ void __launch_bounds__(THREADS)
onehot_chunk_kernel(const int* __restrict__ x, float4* __restrict__ out)
{
    const int tid = threadIdx.x;
    const int lo  = blockIdx.x * CHUNK;                // < 2^27, fits int

    // Rows overlapped by [lo, lo+CHUNK): at most 2.
    const int r0 = lo / NC4;
    const int r1 = (lo + CHUNK - 1) / NC4;

    const int t0 = __ldg(x + r0);                      // broadcast loads,
    const int t1 = (r1 != r0) ? __ldg(x + r1) : t0;    // in flight during fill

    float4* p = out + lo;
    const float4 z = make_float4(0.f, 0.f, 0.f, 0.f);

#pragma unroll
    for (int i = 0; i < ITERS; ++i) {
        __stcs(p + i * THREADS + tid, z);              // evict-first streaming
    }

    // Hot-slot overwrites (<= 2 candidate slots per block).
    {
        const int s = r0 * NC4 + (t0 >> 2) - lo;       // offset within chunk
        if (s >= 0 && s < CHUNK && (s & (THREADS - 1)) == tid)
            reinterpret_cast<float*>(p + s)[t0 & 3] = 1.0f;
    }
    if (r1 != r0) {
        const int s = r1 * NC4 + (t1 >> 2) - lo;
        if (s >= 0 && s < CHUNK && (s & (THREADS - 1)) == tid)
            reinterpret_cast<float*>(p + s)[t1 & 3] = 1.0f;
    }
}

extern "C" void kernel_launch(void* const* d_in, const int* in_sizes, int n_in,
                              void* d_out, int out_size)
{
    const int* x = (const int*)d_in[0];
    onehot_chunk_kernel<<<BLOCKS, THREADS>>>(x, (float4*)d_out);
}

// round 10
// speedup vs baseline: 1.0005x; 1.0005x over previous
#include <cuda_runtime.h>
#include <cuda_bf16.h>

// One-hot: x [8,1024] int32 -> out [8,1024,32000] fp32 (1.048 GB of stores).
// Blackwell 256-bit stores: st.global.cs.v8.f32 (SASS STG.E.256) — one warp
// instruction writes 1024 B = a full L1tex wavefront, halving store-instr
// and wavefront count vs STG.128. Geometry: uniform 1024-float4 chunks,
// 64,000 identical blocks x 256 threads x 2 v8-stores, no tail/predicates.
// f4 slot s is zeroed by thread (s>>1) & 255; that same thread performs the
// 1.0f hot-lane overwrite (same-thread same-address => ordered, no fence).

static constexpr int NUM_CLASS = 32000;
static constexpr int NC4       = NUM_CLASS / 4;        // 8000 float4 per row
static constexpr int ROWS      = 8 * 1024;             // 8192
static constexpr int CHUNK     = 1024;                 // float4 per block
static constexpr int THREADS   = 256;
static constexpr int BLOCKS    = ROWS * NC4 / CHUNK;   // 64,000 exact

__device__ __forceinline__ void stg256_zero_cs(float* p)
{
    asm volatile(
        "st.global.cs.v8.f32 [%0], {%1,%1,%1,%1,%1,%1,%1,%1};"
        :: "l"(p), "f"(0.0f) : "memory");
}

__global__ void __launch_bounds__(THREADS)
onehot_v8_kernel(const int* __restrict__ x, float4* __restrict__ out)
{
    const int tid = threadIdx.x;
    const int lo  = blockIdx.x * CHUNK;                // f4 index, fits int

    // Rows overlapped by [lo, lo+CHUNK): at most 2.
    const int r0 = lo / NC4;
    const int r1 = (lo + CHUNK - 1) / NC4;

    const int t0 = __ldg(x + r0);                      // broadcast loads in
    const int t1 = (r1 != r0) ? __ldg(x + r1) : t0;    // flight during fill

    float4* p = out + lo;

    // 2 x 256-bit stores per thread: thread tid zero-fills f4 slots
    // {2*tid, 2*tid+1} and {512 + 2*tid, 512 + 2*tid+1}.
    stg256_zero_cs(reinterpret_cast<float*>(p + 2 * tid));
    stg256_zero_cs(reinterpret_cast<float*>(p + 512 + 2 * tid));

    // Hot-slot overwrites (<= 2 candidates). Owner of f4 slot s within the
    // chunk is thread (s>>1) & 255 (both halves map the same way).
    {
        const int s = r0 * NC4 + (t0 >> 2) - lo;
        if (s >= 0 && s < CHUNK && ((s >> 1) & (THREADS - 1)) == tid)
            reinterpret_cast<float*>(p + s)[t0 & 3] = 1.0f;
    }
    if (r1 != r0) {
        const int s = r1 * NC4 + (t1 >> 2) - lo;
        if (s >= 0 && s < CHUNK && ((s >> 1) & (THREADS - 1)) == tid)
            reinterpret_cast<float*>(p + s)[t1 & 3] = 1.0f;
    }
}

extern "C" void kernel_launch(void* const* d_in, const int* in_sizes, int n_in,
                              void* d_out, int out_size)
{
    const int* x = (const int*)d_in[0];
    onehot_v8_kernel<<<BLOCKS, THREADS>>>(x, (float4*)d_out);
}